// round 14
// baseline (speedup 1.0000x reference)
#include <cuda_runtime.h>
#include <cuda_bf16.h>
#include <cuda_fp16.h>
#include <cstdint>

#define N_NODES 100000
#define NPAD    100096
#define DIM 128
#define NUM_LABELS 1024
#define MAX_E 1700000
#define SCAN_BLOCKS 98   // 98 * 1024 = 100352 >= NPAD

// ---------------- scratch ----------------
__device__ float4   g_h1  [ (size_t)N_NODES * (DIM/4) ];
__device__ uint32_t g_gin_h [(size_t)NPAD * 64];
__device__ uint32_t g_gin_l [(size_t)NPAD * 64];
__device__ uint32_t g_pool_h[(size_t)NPAD * 64];
__device__ uint32_t g_pool_l[(size_t)NPAD * 64];
// CSR by dst
__device__ int g_deg   [NPAD];
__device__ int g_rowptr[NPAD + 1];
__device__ int g_cursor[NPAD];
__device__ int g_csrsrc[MAX_E];
__device__ int g_bsum  [SCAN_BLOCKS];
__device__ int g_boff  [SCAN_BLOCKS];
// pre-split transposed weights (bf16 x4 small, fp16-hi for lin)
#define OFF_W1  0
#define OFF_RW1 8192
#define OFF_W2  16384
#define OFF_RW2 24576
#define OFF_LIN 32768
__device__ uint32_t g_wb_h[98304];
__device__ uint32_t g_wb_l[32768];
__device__ int      g_idx64;

// ---------------- helpers ----------------
__device__ __forceinline__ uint32_t smem_to_u32(const void* p) {
    uint32_t a;
    asm("{ .reg .u64 t; cvta.to.shared.u64 t, %1; cvt.u32.u64 %0, t; }" : "=r"(a) : "l"(p));
    return a;
}
__device__ __forceinline__ void split2(float x, float y, uint32_t& hi, uint32_t& lo) {
    __nv_bfloat16 hx = __float2bfloat16(x);
    __nv_bfloat16 hy = __float2bfloat16(y);
    __nv_bfloat16 lx = __float2bfloat16(x - __bfloat162float(hx));
    __nv_bfloat16 ly = __float2bfloat16(y - __bfloat162float(hy));
    hi = ((uint32_t)__bfloat16_as_ushort(hy) << 16) | (uint32_t)__bfloat16_as_ushort(hx);
    lo = ((uint32_t)__bfloat16_as_ushort(ly) << 16) | (uint32_t)__bfloat16_as_ushort(lx);
}
__device__ __forceinline__ void split2h(float x, float y, uint32_t& hi, uint32_t& lo) {
    __half hx = __float2half_rn(x);
    __half hy = __float2half_rn(y);
    __half lx = __float2half_rn(x - __half2float(hx));
    __half ly = __float2half_rn(y - __half2float(hy));
    hi = ((uint32_t)__half_as_ushort(hy) << 16) | (uint32_t)__half_as_ushort(hx);
    lo = ((uint32_t)__half_as_ushort(ly) << 16) | (uint32_t)__half_as_ushort(lx);
}
__device__ __forceinline__ float bf_lo(uint32_t v) {
    return __bfloat162float(__ushort_as_bfloat16((unsigned short)(v & 0xFFFF)));
}
__device__ __forceinline__ float bf_hi(uint32_t v) {
    return __bfloat162float(__ushort_as_bfloat16((unsigned short)(v >> 16)));
}
__device__ __forceinline__ void mma_bf16(float* d, const uint32_t* a, const uint32_t* b) {
    asm volatile(
        "mma.sync.aligned.m16n8k16.row.col.f32.bf16.bf16.f32 "
        "{%0,%1,%2,%3}, {%4,%5,%6,%7}, {%8,%9}, {%0,%1,%2,%3};"
        : "+f"(d[0]), "+f"(d[1]), "+f"(d[2]), "+f"(d[3])
        : "r"(a[0]), "r"(a[1]), "r"(a[2]), "r"(a[3]), "r"(b[0]), "r"(b[1]));
}
__device__ __forceinline__ void mma_f16(float* d, const uint32_t* a, const uint32_t* b) {
    asm volatile(
        "mma.sync.aligned.m16n8k16.row.col.f32.f16.f16.f32 "
        "{%0,%1,%2,%3}, {%4,%5,%6,%7}, {%8,%9}, {%0,%1,%2,%3};"
        : "+f"(d[0]), "+f"(d[1]), "+f"(d[2]), "+f"(d[3])
        : "r"(a[0]), "r"(a[1]), "r"(a[2]), "r"(a[3]), "r"(b[0]), "r"(b[1]));
}
__device__ __forceinline__ void ldsm4(uint32_t* r, uint32_t addr) {
    asm volatile("ldmatrix.sync.aligned.m8n8.x4.shared.b16 {%0,%1,%2,%3}, [%4];"
        : "=r"(r[0]), "=r"(r[1]), "=r"(r[2]), "=r"(r[3]) : "r"(addr));
}
__device__ __forceinline__ void ldsm2(uint32_t* r, uint32_t addr) {
    asm volatile("ldmatrix.sync.aligned.m8n8.x2.shared.b16 {%0,%1}, [%2];"
        : "=r"(r[0]), "=r"(r[1]) : "r"(addr));
}
#define CPA16(dst, src) \
    asm volatile("cp.async.ca.shared.global [%0], [%1], 16;" :: "r"(dst), "l"(src) : "memory")

__device__ __forceinline__ long long edge_idx(const void* p, int i) {
    return g_idx64 ? ((const long long*)p)[i] : (long long)((const int*)p)[i];
}

// ---------------- index-width detection ----------------
__global__ void detect_kernel(const unsigned long long* __restrict__ src) {
    if (threadIdx.x == 0 && blockIdx.x == 0) {
        int is64 = 1;
        for (int i = 0; i < 64; i++) {
            if (src[i] >> 32) { is64 = 0; break; }
        }
        g_idx64 = is64;
    }
}

// ---------------- merged prep: weight splits + deg zero ----------------
__global__ void prep_kernel(const float* __restrict__ W1,  const float* __restrict__ rW1,
                            const float* __restrict__ W2,  const float* __restrict__ rW2,
                            const float* __restrict__ linW)
{
    int idx = blockIdx.x * blockDim.x + threadIdx.x;
    if (idx < 32768) {
        int which = idx >> 13;
        int t = idx & 8191;
        const float* W = (which == 0) ? W1 : (which == 1) ? rW1 : (which == 2) ? W2 : rW2;
        int off = which * 8192;
        int n = t & 127;
        int p = t >> 7;
        float x = W[(size_t)(2 * p)     * 128 + n];
        float y = W[(size_t)(2 * p + 1) * 128 + n];
        uint32_t h, l;
        split2(x, y, h, l);
        int chunk = p >> 4, j = p & 15;
        g_wb_h[off + ((size_t)chunk * 128 + n) * 16 + j] = h;
        g_wb_l[off + ((size_t)chunk * 128 + n) * 16 + j] = l;
    } else if (idx < 32768 + 65536) {
        int t = idx - 32768;
        int n = t & 1023;
        int p = t >> 10;
        __half x = __float2half_rn(linW[(size_t)(2 * p)     * 1024 + n]);
        __half y = __float2half_rn(linW[(size_t)(2 * p + 1) * 1024 + n]);
        uint32_t h = ((uint32_t)__half_as_ushort(y) << 16) | (uint32_t)__half_as_ushort(x);
        int chunk = p >> 4, j = p & 15;
        g_wb_h[OFF_LIN + ((size_t)chunk * 1024 + n) * 16 + j] = h;
    } else {
        int t = idx - (32768 + 65536);
        if (t < NPAD) g_deg[t] = 0;
    }
}
#define PREP_TOTAL (32768 + 65536 + NPAD)

// ---------------- CSR build ----------------
__global__ void hist_kernel(const void* __restrict__ dstv, int nE) {
    int i = blockIdx.x * blockDim.x + threadIdx.x;
    int stride = gridDim.x * blockDim.x;
    for (; i < nE; i += stride) {
        int d = (int)edge_idx(dstv, i);
        atomicAdd(&g_deg[d], 1);
    }
}

// ---- parallel 3-phase scan ----
__global__ __launch_bounds__(1024) void scanA_kernel(int n) {
    __shared__ int ss[1024];
    int b = blockIdx.x, t = threadIdx.x;
    int i = b * 1024 + t;
    int v = (i < n) ? g_deg[i] : 0;
    ss[t] = v;
    __syncthreads();
    #pragma unroll
    for (int off = 1; off < 1024; off <<= 1) {
        int u = (t >= off) ? ss[t - off] : 0;
        __syncthreads();
        ss[t] += u;
        __syncthreads();
    }
    if (i < n) g_rowptr[i] = ss[t];
    if (t == 1023) g_bsum[b] = ss[t];
}
__global__ __launch_bounds__(128) void scanB_kernel(int n) {
    __shared__ int ss[128];
    int t = threadIdx.x;
    ss[t] = (t < SCAN_BLOCKS) ? g_bsum[t] : 0;
    __syncthreads();
    #pragma unroll
    for (int off = 1; off < 128; off <<= 1) {
        int u = (t >= off) ? ss[t - off] : 0;
        __syncthreads();
        ss[t] += u;
        __syncthreads();
    }
    if (t < SCAN_BLOCKS) g_boff[t] = ss[t] - g_bsum[t];
    if (t == 127) g_rowptr[n] = ss[t];
}
__global__ __launch_bounds__(1024) void scanC_kernel(int n) {
    int i = blockIdx.x * 1024 + threadIdx.x;
    if (i >= n) return;
    int ex = g_boff[blockIdx.x] + g_rowptr[i] - g_deg[i];
    g_rowptr[i] = ex;
    g_cursor[i] = ex;
}

__global__ void fill_kernel(const void* __restrict__ srcv,
                            const void* __restrict__ dstv, int nE) {
    int i = blockIdx.x * blockDim.x + threadIdx.x;
    int stride = gridDim.x * blockDim.x;
    for (; i < nE; i += stride) {
        int d = (int)edge_idx(dstv, i);
        int s = (int)edge_idx(srcv, i);
        int pos = atomicAdd(&g_cursor[d], 1);
        g_csrsrc[pos] = s;
    }
}

// ---------------- aggregation: one warp per node ----------------
__global__ void agg_kernel(const float4* __restrict__ h,
                           const float* __restrict__ epsp,
                           uint32_t* __restrict__ outh,
                           uint32_t* __restrict__ outl,
                           int M)
{
    int node = (blockIdx.x * blockDim.x + threadIdx.x) >> 5;
    int lane = threadIdx.x & 31;
    if (node >= M) return;
    const float eps1 = 1.0f + epsp[0];

    float4 acc = h[(size_t)node * 32 + lane];
    acc.x *= eps1; acc.y *= eps1; acc.z *= eps1; acc.w *= eps1;

    int e   = g_rowptr[node];
    int end = g_rowptr[node + 1];
    // unroll-8 for deeper MLP
    for (; e + 8 <= end; e += 8) {
        int s0 = g_csrsrc[e],     s1 = g_csrsrc[e + 1], s2 = g_csrsrc[e + 2], s3 = g_csrsrc[e + 3];
        int s4 = g_csrsrc[e + 4], s5 = g_csrsrc[e + 5], s6 = g_csrsrc[e + 6], s7 = g_csrsrc[e + 7];
        float4 v0 = h[(size_t)s0 * 32 + lane];
        float4 v1 = h[(size_t)s1 * 32 + lane];
        float4 v2 = h[(size_t)s2 * 32 + lane];
        float4 v3 = h[(size_t)s3 * 32 + lane];
        float4 v4 = h[(size_t)s4 * 32 + lane];
        float4 v5 = h[(size_t)s5 * 32 + lane];
        float4 v6 = h[(size_t)s6 * 32 + lane];
        float4 v7 = h[(size_t)s7 * 32 + lane];
        acc.x += (v0.x + v1.x) + (v2.x + v3.x) + (v4.x + v5.x) + (v6.x + v7.x);
        acc.y += (v0.y + v1.y) + (v2.y + v3.y) + (v4.y + v5.y) + (v6.y + v7.y);
        acc.z += (v0.z + v1.z) + (v2.z + v3.z) + (v4.z + v5.z) + (v6.z + v7.z);
        acc.w += (v0.w + v1.w) + (v2.w + v3.w) + (v4.w + v5.w) + (v6.w + v7.w);
    }
    for (; e + 4 <= end; e += 4) {
        int s0 = g_csrsrc[e], s1 = g_csrsrc[e + 1], s2 = g_csrsrc[e + 2], s3 = g_csrsrc[e + 3];
        float4 v0 = h[(size_t)s0 * 32 + lane];
        float4 v1 = h[(size_t)s1 * 32 + lane];
        float4 v2 = h[(size_t)s2 * 32 + lane];
        float4 v3 = h[(size_t)s3 * 32 + lane];
        acc.x += v0.x + v1.x + v2.x + v3.x;
        acc.y += v0.y + v1.y + v2.y + v3.y;
        acc.z += v0.z + v1.z + v2.z + v3.z;
        acc.w += v0.w + v1.w + v2.w + v3.w;
    }
    for (; e < end; e++) {
        int s = g_csrsrc[e];
        float4 v = h[(size_t)s * 32 + lane];
        acc.x += v.x; acc.y += v.y; acc.z += v.z; acc.w += v.w;
    }

    uint32_t h0, l0, h1v, l1v;
    split2(acc.x, acc.y, h0, l0);
    split2(acc.z, acc.w, h1v, l1v);
    size_t o = (size_t)node * 64 + lane * 2;
    *(uint2*)&outh[o] = make_uint2(h0, h1v);
    *(uint2*)&outl[o] = make_uint2(l0, l1v);
}

// ======================= fused layer kernel ===================================
#define SROW 20
#define TROW 68
#define TILE_U32 (128 * SROW)
#define SM_FUSED 110592

template <int LAYER>
__global__ __launch_bounds__(256)
void fused_layer(const uint32_t* __restrict__ Ah,
                 const uint32_t* __restrict__ Al,
                 const uint32_t* __restrict__ Wh,
                 const uint32_t* __restrict__ Wl,
                 const float* __restrict__ b,
                 const uint32_t* __restrict__ rWh,
                 const uint32_t* __restrict__ rWl,
                 const float* __restrict__ rb,
                 float* __restrict__ h1io,
                 uint32_t* __restrict__ poolh,
                 uint32_t* __restrict__ pooll,
                 int M)
{
    extern __shared__ uint32_t smem_u[];
    const int tid  = threadIdx.x;
    const int wid  = tid >> 5;
    const int lane = tid & 31;
    const int row0 = blockIdx.y * 128;
    const int warp_m = (wid & 1) * 64;
    const int warp_n = (wid >> 1) * 32;
    const uint32_t sbase = smem_to_u32(smem_u);
    const int lr = lane >> 2;
    const int lc = lane & 3;
    const int a_rowp = lane & 15;
    const int a_colp = (lane >> 4) << 2;
    const int b_rowp = lane & 7;
    const int b_colp = ((lane >> 3) & 1) << 2;

    uint32_t* sB2 = smem_u;
    uint32_t* sTh = smem_u + 4 * TILE_U32;
    uint32_t* sTl = sTh + 128 * TROW;
    const uint32_t sTh_a = sbase + (uint32_t)(4 * TILE_U32) * 4;
    const uint32_t sTl_a = sTh_a + (uint32_t)(128 * TROW) * 4;

    float acc[4][4][4];
    #pragma unroll
    for (int mi = 0; mi < 4; mi++)
        #pragma unroll
        for (int ni = 0; ni < 4; ni++)
            #pragma unroll
            for (int r = 0; r < 4; r++) acc[mi][ni][r] = 0.f;

    auto issue1 = [&](int c, int stage) {
        #pragma unroll
        for (int i = 0; i < 8; i++) {
            int idx  = tid + i * 256;
            int tile = idx >> 9;
            int r    = idx & 511;
            int row  = r >> 2;
            int j4   = r & 3;
            const uint32_t* g;
            if (tile == 0)      g = Ah + (size_t)(row0 + row) * 64 + c * 16 + j4 * 4;
            else if (tile == 1) g = Al + (size_t)(row0 + row) * 64 + c * 16 + j4 * 4;
            else if (tile == 2) g = Wh + ((size_t)c * 128 + row) * 16 + j4 * 4;
            else                g = Wl + ((size_t)c * 128 + row) * 16 + j4 * 4;
            uint32_t d = sbase + (uint32_t)(stage * 4 * TILE_U32 + tile * TILE_U32 + row * SROW + j4 * 4) * 4;
            CPA16(d, g);
        }
        asm volatile("cp.async.commit_group;" ::: "memory");
    };

    auto mma_block = [&](uint32_t aHi, uint32_t aLo, uint32_t bHi, uint32_t bLo,
                         int astride, int acol0) {
        #pragma unroll
        for (int s = 0; s < 2; s++) {
            const int cb = s * 8;
            uint32_t Bfh[4][2], Bfl[4][2];
            #pragma unroll
            for (int ni = 0; ni < 4; ni++) {
                uint32_t off = (uint32_t)((warp_n + ni * 8 + b_rowp) * SROW + cb + b_colp) * 4;
                ldsm2(Bfh[ni], bHi + off);
                ldsm2(Bfl[ni], bLo + off);
            }
            uint32_t Afh[4][4], Afl[4][4];
            #pragma unroll
            for (int mi = 0; mi < 4; mi++) {
                uint32_t off = (uint32_t)((warp_m + mi * 16 + a_rowp) * astride + acol0 + cb + a_colp) * 4;
                ldsm4(Afh[mi], aHi + off);
                ldsm4(Afl[mi], aLo + off);
            }
            #pragma unroll
            for (int mi = 0; mi < 4; mi++)
                #pragma unroll
                for (int ni = 0; ni < 4; ni++)
                    mma_bf16(acc[mi][ni], Afh[mi], Bfh[ni]);
            #pragma unroll
            for (int mi = 0; mi < 4; mi++)
                #pragma unroll
                for (int ni = 0; ni < 4; ni++)
                    mma_bf16(acc[mi][ni], Afh[mi], Bfl[ni]);
            #pragma unroll
            for (int mi = 0; mi < 4; mi++)
                #pragma unroll
                for (int ni = 0; ni < 4; ni++)
                    mma_bf16(acc[mi][ni], Afl[mi], Bfh[ni]);
        }
    };

    // ================= phase 1 =================
    issue1(0, 0);
    #pragma unroll 1
    for (int c = 0; c < 4; c++) {
        const int stage = c & 1;
        const uint32_t st = sbase + (uint32_t)(stage * 4 * TILE_U32) * 4;
        if (c + 1 < 4) {
            issue1(c + 1, (c + 1) & 1);
            asm volatile("cp.async.wait_group 1;" ::: "memory");
        } else {
            asm volatile("cp.async.wait_group 0;" ::: "memory");
        }
        __syncthreads();
        mma_block(st, st + TILE_U32 * 4, st + 2 * TILE_U32 * 4, st + 3 * TILE_U32 * 4, SROW, 0);
        __syncthreads();
    }

    auto issue2 = [&](int c, int stage) {
        #pragma unroll
        for (int i = 0; i < 4; i++) {
            int idx  = tid + i * 256;
            int tile = idx >> 9;
            int r    = idx & 511;
            int row  = r >> 2;
            int j4   = r & 3;
            const uint32_t* g = (tile ? rWl : rWh) + ((size_t)c * 128 + row) * 16 + j4 * 4;
            uint32_t d = sbase + (uint32_t)(stage * 2 * TILE_U32 + tile * TILE_U32 + row * SROW + j4 * 4) * 4;
            CPA16(d, g);
        }
        asm volatile("cp.async.commit_group;" ::: "memory");
    };
    issue2(0, 0);

    // ---- epilogue1 ----
    #pragma unroll
    for (int mi = 0; mi < 4; mi++) {
        #pragma unroll
        for (int half = 0; half < 2; half++) {
            int m = warp_m + mi * 16 + half * 8 + lr;
            #pragma unroll
            for (int ni = 0; ni < 4; ni++) {
                int gn = warp_n + ni * 8 + lc * 2;
                float2 bb = *(const float2*)(b + gn);
                float tx = fmaxf(acc[mi][ni][half * 2 + 0] + bb.x, 0.f);
                float ty = fmaxf(acc[mi][ni][half * 2 + 1] + bb.y, 0.f);
                uint32_t h, l;
                split2(tx, ty, h, l);
                int o = m * TROW + (warp_n >> 1) + ni * 4 + lc;
                sTh[o] = h;
                sTl[o] = l;
            }
        }
    }
    #pragma unroll
    for (int mi = 0; mi < 4; mi++)
        #pragma unroll
        for (int ni = 0; ni < 4; ni++)
            #pragma unroll
            for (int r = 0; r < 4; r++) acc[mi][ni][r] = 0.f;
    __syncthreads();

    // ================= phase 2 =================
    #pragma unroll 1
    for (int c = 0; c < 4; c++) {
        const int stage = c & 1;
        const uint32_t st = sbase + (uint32_t)(stage * 2 * TILE_U32) * 4;
        if (c + 1 < 4) {
            issue2(c + 1, (c + 1) & 1);
            asm volatile("cp.async.wait_group 1;" ::: "memory");
        } else {
            asm volatile("cp.async.wait_group 0;" ::: "memory");
        }
        __syncthreads();
        mma_block(sTh_a, sTl_a, st, st + TILE_U32 * 4, TROW, c * 16);
        __syncthreads();
    }

    // ---- epilogue2 ----
    #pragma unroll
    for (int mi = 0; mi < 4; mi++) {
        #pragma unroll
        for (int half = 0; half < 2; half++) {
            int m  = warp_m + mi * 16 + half * 8 + lr;
            int gm = row0 + m;
            if (gm >= M) continue;
            #pragma unroll
            for (int ni = 0; ni < 4; ni++) {
                int gn = warp_n + ni * 8 + lc * 2;
                float2 rr;
                float2 bb = *(const float2*)(rb + gn);
                rr.x = fmaxf(acc[mi][ni][half * 2 + 0] + bb.x, 0.f);
                rr.y = fmaxf(acc[mi][ni][half * 2 + 1] + bb.y, 0.f);
                int o = m * TROW + (warp_n >> 1) + ni * 4 + lc;
                uint32_t th = sTh[o], tl = sTl[o];
                float tx = bf_lo(th) + bf_lo(tl);
                float ty = bf_hi(th) + bf_hi(tl);
                if (LAYER == 0) {
                    rr.x += tx; rr.y += ty;
                    *(float2*)(h1io + (size_t)gm * DIM + gn) = rr;
                } else {
                    float2 hh = *(const float2*)(h1io + (size_t)gm * DIM + gn);
                    rr.x = 0.5f * (rr.x + tx + hh.x);
                    rr.y = 0.5f * (rr.y + ty + hh.y);
                    uint32_t ph, pl;
                    split2h(rr.x, rr.y, ph, pl);
                    size_t oidx = (size_t)gm * 64 + (gn >> 1);
                    poolh[oidx] = ph;
                    pooll[oidx] = pl;
                }
            }
        }
    }
}

// ======================= head GEMM: 256x128 tile, fp16 2-term =================
// 512 threads, 16 warps (4m x 4n), warp tile 64x32. A tile resident per 4-chunk
// K loop; 2-stage cp.async. smem/stage = Ahi(256xSROW) + Alo + B(128xSROW).
#define HSTAGE (2 * 256 * SROW + 128 * SROW)      // 12800 u32
#define SM_HEAD (2 * HSTAGE * 4)                  // 102400 B

__global__ __launch_bounds__(512)
void gemm_head(const uint32_t* __restrict__ Ah,
               const uint32_t* __restrict__ Al,
               const uint32_t* __restrict__ Bh,
               const float* __restrict__ bias,
               float* __restrict__ out,
               int M)
{
    extern __shared__ uint32_t smem_u[];
    const int tid  = threadIdx.x;
    const int wid  = tid >> 5;
    const int lane = tid & 31;
    const int row0 = blockIdx.y * 256;
    const int col0 = blockIdx.x * 128;
    const int warp_m = (wid & 3) * 64;
    const int warp_n = (wid >> 2) * 32;
    const uint32_t sbase = smem_to_u32(smem_u);
    const int lr = lane >> 2;
    const int lc = lane & 3;
    const int a_rowp = lane & 15;
    const int a_colp = (lane >> 4) << 2;
    const int b_rowp = lane & 7;
    const int b_colp = ((lane >> 3) & 1) << 2;

    float acc[4][4][4];
    #pragma unroll
    for (int mi = 0; mi < 4; mi++)
        #pragma unroll
        for (int ni = 0; ni < 4; ni++)
            #pragma unroll
            for (int r = 0; r < 4; r++) acc[mi][ni][r] = 0.f;

    // per stage: Ahi at 0 (256*SROW), Alo at 256*SROW, B at 2*256*SROW
    auto issue = [&](int c, int stage) {
        #pragma unroll
        for (int i = 0; i < 5; i++) {
            int idx = tid + i * 512;            // 0..2559 16B units
            uint32_t soff;
            const uint32_t* g;
            if (idx < 1024) {
                int row = idx >> 2, j4 = idx & 3;
                g = Ah + (size_t)(row0 + row) * 64 + c * 16 + j4 * 4;
                soff = (uint32_t)(row * SROW + j4 * 4);
            } else if (idx < 2048) {
                int r = idx - 1024;
                int row = r >> 2, j4 = r & 3;
                g = Al + (size_t)(row0 + row) * 64 + c * 16 + j4 * 4;
                soff = (uint32_t)(256 * SROW + row * SROW + j4 * 4);
            } else {
                int r = idx - 2048;
                int row = r >> 2, j4 = r & 3;
                g = Bh + ((size_t)c * NUM_LABELS + col0 + row) * 16 + j4 * 4;
                soff = (uint32_t)(2 * 256 * SROW + row * SROW + j4 * 4);
            }
            CPA16(sbase + (uint32_t)(stage * HSTAGE) * 4 + soff * 4, g);
        }
        asm volatile("cp.async.commit_group;" ::: "memory");
    };

    issue(0, 0);
    #pragma unroll 1
    for (int c = 0; c < 4; c++) {
        const int stage = c & 1;
        const uint32_t sA_hi = sbase + (uint32_t)(stage * HSTAGE) * 4;
        const uint32_t sA_lo = sA_hi + (uint32_t)(256 * SROW) * 4;
        const uint32_t sB_hi = sA_hi + (uint32_t)(2 * 256 * SROW) * 4;
        if (c + 1 < 4) {
            issue(c + 1, (c + 1) & 1);
            asm volatile("cp.async.wait_group 1;" ::: "memory");
        } else {
            asm volatile("cp.async.wait_group 0;" ::: "memory");
        }
        __syncthreads();

        #pragma unroll
        for (int s = 0; s < 2; s++) {
            const int cb = s * 8;
            uint32_t Bf[4][2];
            #pragma unroll
            for (int ni = 0; ni < 4; ni++) {
                uint32_t off = (uint32_t)((warp_n + ni * 8 + b_rowp) * SROW + cb + b_colp) * 4;
                ldsm2(Bf[ni], sB_hi + off);
            }
            uint32_t Afh[4][4], Afl[4][4];
            #pragma unroll
            for (int mi = 0; mi < 4; mi++) {
                uint32_t off = (uint32_t)((warp_m + mi * 16 + a_rowp) * SROW + cb + a_colp) * 4;
                ldsm4(Afh[mi], sA_hi + off);
                ldsm4(Afl[mi], sA_lo + off);
            }
            #pragma unroll
            for (int mi = 0; mi < 4; mi++)
                #pragma unroll
                for (int ni = 0; ni < 4; ni++)
                    mma_f16(acc[mi][ni], Afh[mi], Bf[ni]);
            #pragma unroll
            for (int mi = 0; mi < 4; mi++)
                #pragma unroll
                for (int ni = 0; ni < 4; ni++)
                    mma_f16(acc[mi][ni], Afl[mi], Bf[ni]);
        }
        __syncthreads();
    }

    #pragma unroll
    for (int mi = 0; mi < 4; mi++) {
        #pragma unroll
        for (int half = 0; half < 2; half++) {
            int gm = row0 + warp_m + mi * 16 + half * 8 + lr;
            if (gm >= M) continue;
            #pragma unroll
            for (int ni = 0; ni < 4; ni++) {
                int gn = col0 + warp_n + ni * 8 + lc * 2;
                float2 r;
                float2 bb = *(const float2*)(bias + gn);
                r.x = acc[mi][ni][half * 2 + 0] + bb.x;
                r.y = acc[mi][ni][half * 2 + 1] + bb.y;
                *(float2*)(out + (size_t)gm * NUM_LABELS + gn) = r;
            }
        }
    }
}

// ---------------- launch ----------------
extern "C" void kernel_launch(void* const* d_in, const int* in_sizes, int n_in,
                              void* d_out, int out_size)
{
    const float* X    = (const float*)d_in[0];
    const void*  src  = d_in[1];
    const void*  dst  = d_in[2];
    const float* eps1 = (const float*)d_in[3];
    const float* W1   = (const float*)d_in[4];
    const float* b1   = (const float*)d_in[5];
    const float* rW1  = (const float*)d_in[6];
    const float* rb1  = (const float*)d_in[7];
    const float* eps2 = (const float*)d_in[8];
    const float* W2   = (const float*)d_in[9];
    const float* b2   = (const float*)d_in[10];
    const float* rW2  = (const float*)d_in[11];
    const float* rb2  = (const float*)d_in[12];
    const float* linW = (const float*)d_in[13];
    const float* linb = (const float*)d_in[14];
    float* out = (float*)d_out;

    const int M  = in_sizes[0] / DIM;   // 100000
    const int nE = in_sizes[1];         // 1600000

    float4* h14;
    uint32_t *gih, *gil, *plh, *pll, *wbh, *wbl;
    cudaGetSymbolAddress((void**)&h14, g_h1);
    cudaGetSymbolAddress((void**)&gih, g_gin_h);
    cudaGetSymbolAddress((void**)&gil, g_gin_l);
    cudaGetSymbolAddress((void**)&plh, g_pool_h);
    cudaGetSymbolAddress((void**)&pll, g_pool_l);
    cudaGetSymbolAddress((void**)&wbh, g_wb_h);
    cudaGetSymbolAddress((void**)&wbl, g_wb_l);
    float* h1 = (float*)h14;

    cudaFuncSetAttribute(fused_layer<0>, cudaFuncAttributeMaxDynamicSharedMemorySize, SM_FUSED);
    cudaFuncSetAttribute(fused_layer<1>, cudaFuncAttributeMaxDynamicSharedMemorySize, SM_FUSED);
    cudaFuncSetAttribute(gemm_head,      cudaFuncAttributeMaxDynamicSharedMemorySize, SM_HEAD);

    const int mBlocks  = (M + 127) / 128;
    const int mBlocks2 = (M + 255) / 256;
    dim3 gfuse(1, mBlocks);
    dim3 ghead(NUM_LABELS / 128, mBlocks2);
    const int aggBlocks = (M * 32 + 255) / 256;

    detect_kernel<<<1, 32>>>((const unsigned long long*)src);

    prep_kernel<<<(PREP_TOTAL + 255) / 256, 256>>>(W1, rW1, W2, rW2, linW);

    hist_kernel<<<2048, 256>>>(dst, nE);
    scanA_kernel<<<SCAN_BLOCKS, 1024>>>(M);
    scanB_kernel<<<1, 128>>>(M);
    scanC_kernel<<<SCAN_BLOCKS, 1024>>>(M);
    fill_kernel<<<2048, 256>>>(src, dst, nE);

    // layer 1
    agg_kernel<<<aggBlocks, 256>>>((const float4*)X, eps1, gih, gil, M);
    fused_layer<0><<<gfuse, 256, SM_FUSED>>>(gih, gil,
                                             wbh + OFF_W1, wbl + OFF_W1, b1,
                                             wbh + OFF_RW1, wbl + OFF_RW1, rb1,
                                             h1, nullptr, nullptr, M);
    // layer 2
    agg_kernel<<<aggBlocks, 256>>>((const float4*)h1, eps2, gih, gil, M);
    fused_layer<1><<<gfuse, 256, SM_FUSED>>>(gih, gil,
                                             wbh + OFF_W2, wbl + OFF_W2, b2,
                                             wbh + OFF_RW2, wbl + OFF_RW2, rb2,
                                             h1, plh, pll, M);
    // head
    gemm_head<<<ghead, 512, SM_HEAD>>>(plh, pll, wbh + OFF_LIN, linb, out, M);
}

// round 15
// speedup vs baseline: 1.0590x; 1.0590x over previous
#include <cuda_runtime.h>
#include <cuda_bf16.h>
#include <cuda_fp16.h>
#include <cstdint>

#define N_NODES 100000
#define NPAD    100096
#define DIM 128
#define NUM_LABELS 1024
#define MAX_E 1700000
#define SCAN_BLOCKS 98   // 98 * 1024 = 100352 >= NPAD

// ---------------- scratch ----------------
__device__ float4   g_h1  [ (size_t)N_NODES * (DIM/4) ];
__device__ uint32_t g_gin_h [(size_t)NPAD * 64];
__device__ uint32_t g_gin_l [(size_t)NPAD * 64];
__device__ uint32_t g_pool_h[(size_t)NPAD * 64];
__device__ uint32_t g_pool_l[(size_t)NPAD * 64];
// CSR by dst
__device__ int g_deg   [NPAD];
__device__ int g_rowptr[NPAD + 1];
__device__ int g_cursor[NPAD];
__device__ int g_csrsrc[MAX_E];
__device__ int g_bsum  [SCAN_BLOCKS];
__device__ int g_boff  [SCAN_BLOCKS];
// pre-split transposed weights (bf16 x4 small, fp16-hi for lin)
#define OFF_W1  0
#define OFF_RW1 8192
#define OFF_W2  16384
#define OFF_RW2 24576
#define OFF_LIN 32768
__device__ uint32_t g_wb_h[98304];
__device__ uint32_t g_wb_l[32768];
__device__ int      g_idx64;

// ---------------- helpers ----------------
__device__ __forceinline__ uint32_t smem_to_u32(const void* p) {
    uint32_t a;
    asm("{ .reg .u64 t; cvta.to.shared.u64 t, %1; cvt.u32.u64 %0, t; }" : "=r"(a) : "l"(p));
    return a;
}
__device__ __forceinline__ void split2(float x, float y, uint32_t& hi, uint32_t& lo) {
    __nv_bfloat16 hx = __float2bfloat16(x);
    __nv_bfloat16 hy = __float2bfloat16(y);
    __nv_bfloat16 lx = __float2bfloat16(x - __bfloat162float(hx));
    __nv_bfloat16 ly = __float2bfloat16(y - __bfloat162float(hy));
    hi = ((uint32_t)__bfloat16_as_ushort(hy) << 16) | (uint32_t)__bfloat16_as_ushort(hx);
    lo = ((uint32_t)__bfloat16_as_ushort(ly) << 16) | (uint32_t)__bfloat16_as_ushort(lx);
}
__device__ __forceinline__ void split2h(float x, float y, uint32_t& hi, uint32_t& lo) {
    __half hx = __float2half_rn(x);
    __half hy = __float2half_rn(y);
    __half lx = __float2half_rn(x - __half2float(hx));
    __half ly = __float2half_rn(y - __half2float(hy));
    hi = ((uint32_t)__half_as_ushort(hy) << 16) | (uint32_t)__half_as_ushort(hx);
    lo = ((uint32_t)__half_as_ushort(ly) << 16) | (uint32_t)__half_as_ushort(lx);
}
__device__ __forceinline__ float bf_lo(uint32_t v) {
    return __bfloat162float(__ushort_as_bfloat16((unsigned short)(v & 0xFFFF)));
}
__device__ __forceinline__ float bf_hi(uint32_t v) {
    return __bfloat162float(__ushort_as_bfloat16((unsigned short)(v >> 16)));
}
__device__ __forceinline__ void mma_bf16(float* d, const uint32_t* a, const uint32_t* b) {
    asm volatile(
        "mma.sync.aligned.m16n8k16.row.col.f32.bf16.bf16.f32 "
        "{%0,%1,%2,%3}, {%4,%5,%6,%7}, {%8,%9}, {%0,%1,%2,%3};"
        : "+f"(d[0]), "+f"(d[1]), "+f"(d[2]), "+f"(d[3])
        : "r"(a[0]), "r"(a[1]), "r"(a[2]), "r"(a[3]), "r"(b[0]), "r"(b[1]));
}
__device__ __forceinline__ void mma_f16(float* d, const uint32_t* a, const uint32_t* b) {
    asm volatile(
        "mma.sync.aligned.m16n8k16.row.col.f32.f16.f16.f32 "
        "{%0,%1,%2,%3}, {%4,%5,%6,%7}, {%8,%9}, {%0,%1,%2,%3};"
        : "+f"(d[0]), "+f"(d[1]), "+f"(d[2]), "+f"(d[3])
        : "r"(a[0]), "r"(a[1]), "r"(a[2]), "r"(a[3]), "r"(b[0]), "r"(b[1]));
}
__device__ __forceinline__ void ldsm4(uint32_t* r, uint32_t addr) {
    asm volatile("ldmatrix.sync.aligned.m8n8.x4.shared.b16 {%0,%1,%2,%3}, [%4];"
        : "=r"(r[0]), "=r"(r[1]), "=r"(r[2]), "=r"(r[3]) : "r"(addr));
}
__device__ __forceinline__ void ldsm2(uint32_t* r, uint32_t addr) {
    asm volatile("ldmatrix.sync.aligned.m8n8.x2.shared.b16 {%0,%1}, [%2];"
        : "=r"(r[0]), "=r"(r[1]) : "r"(addr));
}
#define CPA16(dst, src) \
    asm volatile("cp.async.ca.shared.global [%0], [%1], 16;" :: "r"(dst), "l"(src) : "memory")

__device__ __forceinline__ long long edge_idx(const void* p, int i) {
    return g_idx64 ? ((const long long*)p)[i] : (long long)((const int*)p)[i];
}

// ---------------- merged prep: weight splits + deg zero + idx-width detect ----
__global__ void prep_kernel(const float* __restrict__ W1,  const float* __restrict__ rW1,
                            const float* __restrict__ W2,  const float* __restrict__ rW2,
                            const float* __restrict__ linW,
                            const unsigned long long* __restrict__ src)
{
    int idx = blockIdx.x * blockDim.x + threadIdx.x;
    if (idx < 32768) {
        int which = idx >> 13;
        int t = idx & 8191;
        const float* W = (which == 0) ? W1 : (which == 1) ? rW1 : (which == 2) ? W2 : rW2;
        int off = which * 8192;
        int n = t & 127;
        int p = t >> 7;
        float x = W[(size_t)(2 * p)     * 128 + n];
        float y = W[(size_t)(2 * p + 1) * 128 + n];
        uint32_t h, l;
        split2(x, y, h, l);
        int chunk = p >> 4, j = p & 15;
        g_wb_h[off + ((size_t)chunk * 128 + n) * 16 + j] = h;
        g_wb_l[off + ((size_t)chunk * 128 + n) * 16 + j] = l;
    } else if (idx < 32768 + 65536) {
        int t = idx - 32768;
        int n = t & 1023;
        int p = t >> 10;
        __half x = __float2half_rn(linW[(size_t)(2 * p)     * 1024 + n]);
        __half y = __float2half_rn(linW[(size_t)(2 * p + 1) * 1024 + n]);
        uint32_t h = ((uint32_t)__half_as_ushort(y) << 16) | (uint32_t)__half_as_ushort(x);
        int chunk = p >> 4, j = p & 15;
        g_wb_h[OFF_LIN + ((size_t)chunk * 1024 + n) * 16 + j] = h;
    } else if (idx < 32768 + 65536 + NPAD) {
        int t = idx - (32768 + 65536);
        g_deg[t] = 0;
    } else if (idx == 32768 + 65536 + NPAD) {
        // int32 vs int64 edge-index detection (see R1 post-mortem)
        int is64 = 1;
        for (int i = 0; i < 64; i++) {
            if (src[i] >> 32) { is64 = 0; break; }
        }
        g_idx64 = is64;
    }
}
#define PREP_TOTAL (32768 + 65536 + NPAD + 1)

// ---------------- CSR build ----------------
__global__ void hist_kernel(const void* __restrict__ dstv, int nE) {
    int i = blockIdx.x * blockDim.x + threadIdx.x;
    int stride = gridDim.x * blockDim.x;
    for (; i < nE; i += stride) {
        int d = (int)edge_idx(dstv, i);
        atomicAdd(&g_deg[d], 1);
    }
}

// ---- parallel 3-phase scan ----
__global__ __launch_bounds__(1024) void scanA_kernel(int n) {
    __shared__ int ss[1024];
    int b = blockIdx.x, t = threadIdx.x;
    int i = b * 1024 + t;
    int v = (i < n) ? g_deg[i] : 0;
    ss[t] = v;
    __syncthreads();
    #pragma unroll
    for (int off = 1; off < 1024; off <<= 1) {
        int u = (t >= off) ? ss[t - off] : 0;
        __syncthreads();
        ss[t] += u;
        __syncthreads();
    }
    if (i < n) g_rowptr[i] = ss[t];
    if (t == 1023) g_bsum[b] = ss[t];
}
__global__ __launch_bounds__(128) void scanB_kernel(int n) {
    __shared__ int ss[128];
    int t = threadIdx.x;
    ss[t] = (t < SCAN_BLOCKS) ? g_bsum[t] : 0;
    __syncthreads();
    #pragma unroll
    for (int off = 1; off < 128; off <<= 1) {
        int u = (t >= off) ? ss[t - off] : 0;
        __syncthreads();
        ss[t] += u;
        __syncthreads();
    }
    if (t < SCAN_BLOCKS) g_boff[t] = ss[t] - g_bsum[t];
    if (t == 127) g_rowptr[n] = ss[t];
}
__global__ __launch_bounds__(1024) void scanC_kernel(int n) {
    int i = blockIdx.x * 1024 + threadIdx.x;
    if (i >= n) return;
    int ex = g_boff[blockIdx.x] + g_rowptr[i] - g_deg[i];
    g_rowptr[i] = ex;
    g_cursor[i] = ex;
}

__global__ void fill_kernel(const void* __restrict__ srcv,
                            const void* __restrict__ dstv, int nE) {
    int i = blockIdx.x * blockDim.x + threadIdx.x;
    int stride = gridDim.x * blockDim.x;
    for (; i < nE; i += stride) {
        int d = (int)edge_idx(dstv, i);
        int s = (int)edge_idx(srcv, i);
        int pos = atomicAdd(&g_cursor[d], 1);
        g_csrsrc[pos] = s;
    }
}

// ---------------- aggregation: one warp per node ----------------
__global__ void agg_kernel(const float4* __restrict__ h,
                           const float* __restrict__ epsp,
                           uint32_t* __restrict__ outh,
                           uint32_t* __restrict__ outl,
                           int M)
{
    int node = (blockIdx.x * blockDim.x + threadIdx.x) >> 5;
    int lane = threadIdx.x & 31;
    if (node >= M) return;
    const float eps1 = 1.0f + epsp[0];

    float4 acc = h[(size_t)node * 32 + lane];
    acc.x *= eps1; acc.y *= eps1; acc.z *= eps1; acc.w *= eps1;

    int e   = g_rowptr[node];
    int end = g_rowptr[node + 1];
    for (; e + 8 <= end; e += 8) {
        int s0 = g_csrsrc[e],     s1 = g_csrsrc[e + 1], s2 = g_csrsrc[e + 2], s3 = g_csrsrc[e + 3];
        int s4 = g_csrsrc[e + 4], s5 = g_csrsrc[e + 5], s6 = g_csrsrc[e + 6], s7 = g_csrsrc[e + 7];
        float4 v0 = h[(size_t)s0 * 32 + lane];
        float4 v1 = h[(size_t)s1 * 32 + lane];
        float4 v2 = h[(size_t)s2 * 32 + lane];
        float4 v3 = h[(size_t)s3 * 32 + lane];
        float4 v4 = h[(size_t)s4 * 32 + lane];
        float4 v5 = h[(size_t)s5 * 32 + lane];
        float4 v6 = h[(size_t)s6 * 32 + lane];
        float4 v7 = h[(size_t)s7 * 32 + lane];
        acc.x += (v0.x + v1.x) + (v2.x + v3.x) + (v4.x + v5.x) + (v6.x + v7.x);
        acc.y += (v0.y + v1.y) + (v2.y + v3.y) + (v4.y + v5.y) + (v6.y + v7.y);
        acc.z += (v0.z + v1.z) + (v2.z + v3.z) + (v4.z + v5.z) + (v6.z + v7.z);
        acc.w += (v0.w + v1.w) + (v2.w + v3.w) + (v4.w + v5.w) + (v6.w + v7.w);
    }
    for (; e + 4 <= end; e += 4) {
        int s0 = g_csrsrc[e], s1 = g_csrsrc[e + 1], s2 = g_csrsrc[e + 2], s3 = g_csrsrc[e + 3];
        float4 v0 = h[(size_t)s0 * 32 + lane];
        float4 v1 = h[(size_t)s1 * 32 + lane];
        float4 v2 = h[(size_t)s2 * 32 + lane];
        float4 v3 = h[(size_t)s3 * 32 + lane];
        acc.x += v0.x + v1.x + v2.x + v3.x;
        acc.y += v0.y + v1.y + v2.y + v3.y;
        acc.z += v0.z + v1.z + v2.z + v3.z;
        acc.w += v0.w + v1.w + v2.w + v3.w;
    }
    for (; e < end; e++) {
        int s = g_csrsrc[e];
        float4 v = h[(size_t)s * 32 + lane];
        acc.x += v.x; acc.y += v.y; acc.z += v.z; acc.w += v.w;
    }

    uint32_t h0, l0, h1v, l1v;
    split2(acc.x, acc.y, h0, l0);
    split2(acc.z, acc.w, h1v, l1v);
    size_t o = (size_t)node * 64 + lane * 2;
    *(uint2*)&outh[o] = make_uint2(h0, h1v);
    *(uint2*)&outl[o] = make_uint2(l0, l1v);
}

// ======================= fused layer kernel ===================================
#define SROW 20
#define TROW 68
#define TILE_U32 (128 * SROW)
#define SM_FUSED 110592

template <int LAYER>
__global__ __launch_bounds__(256)
void fused_layer(const uint32_t* __restrict__ Ah,
                 const uint32_t* __restrict__ Al,
                 const uint32_t* __restrict__ Wh,
                 const uint32_t* __restrict__ Wl,
                 const float* __restrict__ b,
                 const uint32_t* __restrict__ rWh,
                 const uint32_t* __restrict__ rWl,
                 const float* __restrict__ rb,
                 float* __restrict__ h1io,
                 uint32_t* __restrict__ poolh,
                 uint32_t* __restrict__ pooll,
                 int M)
{
    extern __shared__ uint32_t smem_u[];
    const int tid  = threadIdx.x;
    const int wid  = tid >> 5;
    const int lane = tid & 31;
    const int row0 = blockIdx.y * 128;
    const int warp_m = (wid & 1) * 64;
    const int warp_n = (wid >> 1) * 32;
    const uint32_t sbase = smem_to_u32(smem_u);
    const int lr = lane >> 2;
    const int lc = lane & 3;
    const int a_rowp = lane & 15;
    const int a_colp = (lane >> 4) << 2;
    const int b_rowp = lane & 7;
    const int b_colp = ((lane >> 3) & 1) << 2;

    uint32_t* sTh = smem_u + 4 * TILE_U32;
    uint32_t* sTl = sTh + 128 * TROW;
    const uint32_t sTh_a = sbase + (uint32_t)(4 * TILE_U32) * 4;
    const uint32_t sTl_a = sTh_a + (uint32_t)(128 * TROW) * 4;

    float acc[4][4][4];
    #pragma unroll
    for (int mi = 0; mi < 4; mi++)
        #pragma unroll
        for (int ni = 0; ni < 4; ni++)
            #pragma unroll
            for (int r = 0; r < 4; r++) acc[mi][ni][r] = 0.f;

    auto issue1 = [&](int c, int stage) {
        #pragma unroll
        for (int i = 0; i < 8; i++) {
            int idx  = tid + i * 256;
            int tile = idx >> 9;
            int r    = idx & 511;
            int row  = r >> 2;
            int j4   = r & 3;
            const uint32_t* g;
            if (tile == 0)      g = Ah + (size_t)(row0 + row) * 64 + c * 16 + j4 * 4;
            else if (tile == 1) g = Al + (size_t)(row0 + row) * 64 + c * 16 + j4 * 4;
            else if (tile == 2) g = Wh + ((size_t)c * 128 + row) * 16 + j4 * 4;
            else                g = Wl + ((size_t)c * 128 + row) * 16 + j4 * 4;
            uint32_t d = sbase + (uint32_t)(stage * 4 * TILE_U32 + tile * TILE_U32 + row * SROW + j4 * 4) * 4;
            CPA16(d, g);
        }
        asm volatile("cp.async.commit_group;" ::: "memory");
    };

    auto mma_block = [&](uint32_t aHi, uint32_t aLo, uint32_t bHi, uint32_t bLo,
                         int astride, int acol0) {
        #pragma unroll
        for (int s = 0; s < 2; s++) {
            const int cb = s * 8;
            uint32_t Bfh[4][2], Bfl[4][2];
            #pragma unroll
            for (int ni = 0; ni < 4; ni++) {
                uint32_t off = (uint32_t)((warp_n + ni * 8 + b_rowp) * SROW + cb + b_colp) * 4;
                ldsm2(Bfh[ni], bHi + off);
                ldsm2(Bfl[ni], bLo + off);
            }
            uint32_t Afh[4][4], Afl[4][4];
            #pragma unroll
            for (int mi = 0; mi < 4; mi++) {
                uint32_t off = (uint32_t)((warp_m + mi * 16 + a_rowp) * astride + acol0 + cb + a_colp) * 4;
                ldsm4(Afh[mi], aHi + off);
                ldsm4(Afl[mi], aLo + off);
            }
            #pragma unroll
            for (int mi = 0; mi < 4; mi++)
                #pragma unroll
                for (int ni = 0; ni < 4; ni++)
                    mma_bf16(acc[mi][ni], Afh[mi], Bfh[ni]);
            #pragma unroll
            for (int mi = 0; mi < 4; mi++)
                #pragma unroll
                for (int ni = 0; ni < 4; ni++)
                    mma_bf16(acc[mi][ni], Afh[mi], Bfl[ni]);
            #pragma unroll
            for (int mi = 0; mi < 4; mi++)
                #pragma unroll
                for (int ni = 0; ni < 4; ni++)
                    mma_bf16(acc[mi][ni], Afl[mi], Bfh[ni]);
        }
    };

    // ================= phase 1 =================
    issue1(0, 0);
    #pragma unroll 1
    for (int c = 0; c < 4; c++) {
        const int stage = c & 1;
        const uint32_t st = sbase + (uint32_t)(stage * 4 * TILE_U32) * 4;
        if (c + 1 < 4) {
            issue1(c + 1, (c + 1) & 1);
            asm volatile("cp.async.wait_group 1;" ::: "memory");
        } else {
            asm volatile("cp.async.wait_group 0;" ::: "memory");
        }
        __syncthreads();
        mma_block(st, st + TILE_U32 * 4, st + 2 * TILE_U32 * 4, st + 3 * TILE_U32 * 4, SROW, 0);
        __syncthreads();
    }

    auto issue2 = [&](int c, int stage) {
        #pragma unroll
        for (int i = 0; i < 4; i++) {
            int idx  = tid + i * 256;
            int tile = idx >> 9;
            int r    = idx & 511;
            int row  = r >> 2;
            int j4   = r & 3;
            const uint32_t* g = (tile ? rWl : rWh) + ((size_t)c * 128 + row) * 16 + j4 * 4;
            uint32_t d = sbase + (uint32_t)(stage * 2 * TILE_U32 + tile * TILE_U32 + row * SROW + j4 * 4) * 4;
            CPA16(d, g);
        }
        asm volatile("cp.async.commit_group;" ::: "memory");
    };
    issue2(0, 0);

    // ---- epilogue1: T = relu(acc + b) -> smem split; re-zero acc ----
    #pragma unroll
    for (int mi = 0; mi < 4; mi++) {
        #pragma unroll
        for (int half = 0; half < 2; half++) {
            int m = warp_m + mi * 16 + half * 8 + lr;
            #pragma unroll
            for (int ni = 0; ni < 4; ni++) {
                int gn = warp_n + ni * 8 + lc * 2;
                float2 bb = *(const float2*)(b + gn);
                float tx = fmaxf(acc[mi][ni][half * 2 + 0] + bb.x, 0.f);
                float ty = fmaxf(acc[mi][ni][half * 2 + 1] + bb.y, 0.f);
                uint32_t h, l;
                split2(tx, ty, h, l);
                int o = m * TROW + (warp_n >> 1) + ni * 4 + lc;
                sTh[o] = h;
                sTl[o] = l;
            }
        }
    }
    #pragma unroll
    for (int mi = 0; mi < 4; mi++)
        #pragma unroll
        for (int ni = 0; ni < 4; ni++)
            #pragma unroll
            for (int r = 0; r < 4; r++) acc[mi][ni][r] = 0.f;
    __syncthreads();

    // ================= phase 2: acc = T @ rW =================
    #pragma unroll 1
    for (int c = 0; c < 4; c++) {
        const int stage = c & 1;
        const uint32_t st = sbase + (uint32_t)(stage * 2 * TILE_U32) * 4;
        if (c + 1 < 4) {
            issue2(c + 1, (c + 1) & 1);
            asm volatile("cp.async.wait_group 1;" ::: "memory");
        } else {
            asm volatile("cp.async.wait_group 0;" ::: "memory");
        }
        __syncthreads();
        mma_block(sTh_a, sTl_a, st, st + TILE_U32 * 4, TROW, c * 16);
        __syncthreads();
    }

    // ---- epilogue2 ----
    #pragma unroll
    for (int mi = 0; mi < 4; mi++) {
        #pragma unroll
        for (int half = 0; half < 2; half++) {
            int m  = warp_m + mi * 16 + half * 8 + lr;
            int gm = row0 + m;
            if (gm >= M) continue;
            #pragma unroll
            for (int ni = 0; ni < 4; ni++) {
                int gn = warp_n + ni * 8 + lc * 2;
                float2 rr;
                float2 bb = *(const float2*)(rb + gn);
                rr.x = fmaxf(acc[mi][ni][half * 2 + 0] + bb.x, 0.f);
                rr.y = fmaxf(acc[mi][ni][half * 2 + 1] + bb.y, 0.f);
                int o = m * TROW + (warp_n >> 1) + ni * 4 + lc;
                uint32_t th = sTh[o], tl = sTl[o];
                float tx = bf_lo(th) + bf_lo(tl);
                float ty = bf_hi(th) + bf_hi(tl);
                if (LAYER == 0) {
                    rr.x += tx; rr.y += ty;
                    *(float2*)(h1io + (size_t)gm * DIM + gn) = rr;
                } else {
                    float2 hh = *(const float2*)(h1io + (size_t)gm * DIM + gn);
                    rr.x = 0.5f * (rr.x + tx + hh.x);
                    rr.y = 0.5f * (rr.y + ty + hh.y);
                    uint32_t ph, pl;
                    split2h(rr.x, rr.y, ph, pl);
                    size_t oidx = (size_t)gm * 64 + (gn >> 1);
                    poolh[oidx] = ph;
                    pooll[oidx] = pl;
                }
            }
        }
    }
}

// ======================= head GEMM: fp16 2-term (128x128, ldmatrix) ===========
#define SM_HEAD (2 * 3 * TILE_U32 * 4)   // 61440

__global__ __launch_bounds__(256)
void gemm_head(const uint32_t* __restrict__ Ah,
               const uint32_t* __restrict__ Al,
               const uint32_t* __restrict__ Bh,
               const float* __restrict__ bias,
               float* __restrict__ out,
               int M)
{
    extern __shared__ uint32_t smem_u[];
    const int tid  = threadIdx.x;
    const int wid  = tid >> 5;
    const int lane = tid & 31;
    const int row0 = blockIdx.y * 128;
    const int col0 = blockIdx.x * 128;
    const int warp_m = (wid & 1) * 64;
    const int warp_n = (wid >> 1) * 32;
    const uint32_t sbase = smem_to_u32(smem_u);
    const int lr = lane >> 2;
    const int lc = lane & 3;
    const int a_rowp = lane & 15;
    const int a_colp = (lane >> 4) << 2;
    const int b_rowp = lane & 7;
    const int b_colp = ((lane >> 3) & 1) << 2;

    float acc[4][4][4];
    #pragma unroll
    for (int mi = 0; mi < 4; mi++)
        #pragma unroll
        for (int ni = 0; ni < 4; ni++)
            #pragma unroll
            for (int r = 0; r < 4; r++) acc[mi][ni][r] = 0.f;

    auto issue = [&](int c, int stage) {
        #pragma unroll
        for (int i = 0; i < 6; i++) {
            int idx  = tid + i * 256;
            int tile = idx / 512;
            int r    = idx & 511;
            int row  = r >> 2;
            int j4   = r & 3;
            const uint32_t* g;
            if (tile == 0)      g = Ah + (size_t)(row0 + row) * 64 + c * 16 + j4 * 4;
            else if (tile == 1) g = Al + (size_t)(row0 + row) * 64 + c * 16 + j4 * 4;
            else                g = Bh + ((size_t)c * NUM_LABELS + col0 + row) * 16 + j4 * 4;
            uint32_t d = sbase + (uint32_t)(stage * 3 * TILE_U32 + tile * TILE_U32 + row * SROW + j4 * 4) * 4;
            CPA16(d, g);
        }
        asm volatile("cp.async.commit_group;" ::: "memory");
    };

    issue(0, 0);
    #pragma unroll 1
    for (int c = 0; c < 4; c++) {
        const int stage = c & 1;
        const uint32_t sA_hi = sbase + (uint32_t)(stage * 3 * TILE_U32) * 4;
        const uint32_t sA_lo = sA_hi + (uint32_t)TILE_U32 * 4;
        const uint32_t sB_hi = sA_hi + (uint32_t)(2 * TILE_U32) * 4;
        if (c + 1 < 4) {
            issue(c + 1, (c + 1) & 1);
            asm volatile("cp.async.wait_group 1;" ::: "memory");
        } else {
            asm volatile("cp.async.wait_group 0;" ::: "memory");
        }
        __syncthreads();

        #pragma unroll
        for (int s = 0; s < 2; s++) {
            const int cb = s * 8;
            uint32_t Bf[4][2];
            #pragma unroll
            for (int ni = 0; ni < 4; ni++) {
                uint32_t off = (uint32_t)((warp_n + ni * 8 + b_rowp) * SROW + cb + b_colp) * 4;
                ldsm2(Bf[ni], sB_hi + off);
            }
            uint32_t Afh[4][4], Afl[4][4];
            #pragma unroll
            for (int mi = 0; mi < 4; mi++) {
                uint32_t off = (uint32_t)((warp_m + mi * 16 + a_rowp) * SROW + cb + a_colp) * 4;
                ldsm4(Afh[mi], sA_hi + off);
                ldsm4(Afl[mi], sA_lo + off);
            }
            #pragma unroll
            for (int mi = 0; mi < 4; mi++)
                #pragma unroll
                for (int ni = 0; ni < 4; ni++)
                    mma_f16(acc[mi][ni], Afh[mi], Bf[ni]);
            #pragma unroll
            for (int mi = 0; mi < 4; mi++)
                #pragma unroll
                for (int ni = 0; ni < 4; ni++)
                    mma_f16(acc[mi][ni], Afl[mi], Bf[ni]);
        }
        __syncthreads();
    }

    #pragma unroll
    for (int mi = 0; mi < 4; mi++) {
        #pragma unroll
        for (int half = 0; half < 2; half++) {
            int gm = row0 + warp_m + mi * 16 + half * 8 + lr;
            if (gm >= M) continue;
            #pragma unroll
            for (int ni = 0; ni < 4; ni++) {
                int gn = col0 + warp_n + ni * 8 + lc * 2;
                float2 r;
                float2 bb = *(const float2*)(bias + gn);
                r.x = acc[mi][ni][half * 2 + 0] + bb.x;
                r.y = acc[mi][ni][half * 2 + 1] + bb.y;
                *(float2*)(out + (size_t)gm * NUM_LABELS + gn) = r;
            }
        }
    }
}

// ---------------- launch ----------------
extern "C" void kernel_launch(void* const* d_in, const int* in_sizes, int n_in,
                              void* d_out, int out_size)
{
    const float* X    = (const float*)d_in[0];
    const void*  src  = d_in[1];
    const void*  dst  = d_in[2];
    const float* eps1 = (const float*)d_in[3];
    const float* W1   = (const float*)d_in[4];
    const float* b1   = (const float*)d_in[5];
    const float* rW1  = (const float*)d_in[6];
    const float* rb1  = (const float*)d_in[7];
    const float* eps2 = (const float*)d_in[8];
    const float* W2   = (const float*)d_in[9];
    const float* b2   = (const float*)d_in[10];
    const float* rW2  = (const float*)d_in[11];
    const float* rb2  = (const float*)d_in[12];
    const float* linW = (const float*)d_in[13];
    const float* linb = (const float*)d_in[14];
    float* out = (float*)d_out;

    const int M  = in_sizes[0] / DIM;   // 100000
    const int nE = in_sizes[1];         // 1600000

    float4* h14;
    uint32_t *gih, *gil, *plh, *pll, *wbh, *wbl;
    cudaGetSymbolAddress((void**)&h14, g_h1);
    cudaGetSymbolAddress((void**)&gih, g_gin_h);
    cudaGetSymbolAddress((void**)&gil, g_gin_l);
    cudaGetSymbolAddress((void**)&plh, g_pool_h);
    cudaGetSymbolAddress((void**)&pll, g_pool_l);
    cudaGetSymbolAddress((void**)&wbh, g_wb_h);
    cudaGetSymbolAddress((void**)&wbl, g_wb_l);
    float* h1 = (float*)h14;

    cudaFuncSetAttribute(fused_layer<0>, cudaFuncAttributeMaxDynamicSharedMemorySize, SM_FUSED);
    cudaFuncSetAttribute(fused_layer<1>, cudaFuncAttributeMaxDynamicSharedMemorySize, SM_FUSED);
    cudaFuncSetAttribute(gemm_head,      cudaFuncAttributeMaxDynamicSharedMemorySize, SM_HEAD);

    const int mBlocks = (M + 127) / 128;
    dim3 gfuse(1, mBlocks);
    dim3 ghead(NUM_LABELS / 128, mBlocks);
    const int aggBlocks = (M * 32 + 255) / 256;

    prep_kernel<<<(PREP_TOTAL + 255) / 256, 256>>>(W1, rW1, W2, rW2, linW,
                                                   (const unsigned long long*)src);

    hist_kernel<<<2048, 256>>>(dst, nE);
    scanA_kernel<<<SCAN_BLOCKS, 1024>>>(M);
    scanB_kernel<<<1, 128>>>(M);
    scanC_kernel<<<SCAN_BLOCKS, 1024>>>(M);
    fill_kernel<<<2048, 256>>>(src, dst, nE);

    // layer 1
    agg_kernel<<<aggBlocks, 256>>>((const float4*)X, eps1, gih, gil, M);
    fused_layer<0><<<gfuse, 256, SM_FUSED>>>(gih, gil,
                                             wbh + OFF_W1, wbl + OFF_W1, b1,
                                             wbh + OFF_RW1, wbl + OFF_RW1, rb1,
                                             h1, nullptr, nullptr, M);
    // layer 2
    agg_kernel<<<aggBlocks, 256>>>((const float4*)h1, eps2, gih, gil, M);
    fused_layer<1><<<gfuse, 256, SM_FUSED>>>(gih, gil,
                                             wbh + OFF_W2, wbl + OFF_W2, b2,
                                             wbh + OFF_RW2, wbl + OFF_RW2, rb2,
                                             h1, plh, pll, M);
    // head
    gemm_head<<<ghead, 256, SM_HEAD>>>(plh, pll, wbh + OFF_LIN, linb, out, M);
}